// round 5
// baseline (speedup 1.0000x reference)
#include <cuda_runtime.h>

// ARIMA(16,1,16), S = 2^20 diffed samples. ONE fused kernel:
//  per warp (512 warps): coalesced series load -> 18-tap FIR (x = y - AR(y)
//  telescoped onto raw s) -> order-16 IIR in transposed DF2 form, processed
//  2 steps/iter with packed fma.rn.f32x2, W=96 warmup + L=64 main per lane.
//  Block 0 is made EXACT by feeding corrected x values (no guards needed).
//  Last-block-done reduction writes the final mean (no second kernel).

#define S_LEN   1048576
#define WARM    96
#define NWARP   512
#define SPAN    2048                       // main x-values per warp
#define TILE_F  (WARM + SPAN)              // 2144
#define TILE_P  2212                       // covers f(2175)=2208
#define SS_N    2200                       // 550 float4; FIR reads <= 2195

typedef unsigned long long ull;

__device__ float    g_partial[NWARP];
__device__ unsigned g_cnt;                 // zero-init; reset by last block

__device__ __forceinline__ ull pack2(float lo, float hi) {
    ull r; asm("mov.b64 %0, {%1,%2};" : "=l"(r) : "f"(lo), "f"(hi)); return r;
}

// 2 IIR steps: state d0..d15 packed in P[0..7], P[8]=(0,0).
// err = x0 + d0; err1 = x1 + d1 + nc0*err;
// new d_j = d_{j+2} + nc_{j+1}*err + nc_j*err1  (nc16=0, d16=d17=0).
template<bool ACC>
__device__ __forceinline__ void step2(ull* P, const ull* PA, const ull* PB,
                                      float nc0, ull& acc2, float x0, float x1) {
    float d0, d1;
    asm("mov.b64 {%0,%1}, %2;" : "=f"(d0), "=f"(d1) : "l"(P[0]));
    float err  = x0 + d0;
    float err1 = fmaf(nc0, err, x1 + d1);
    ull e2 = pack2(err, err);
    ull f2 = pack2(err1, err1);
#pragma unroll
    for (int k = 0; k < 8; ++k) {
        ull t;
        asm("fma.rn.f32x2 %0, %1, %2, %3;" : "=l"(t)
            : "l"(PA[k]), "l"(e2), "l"(P[k + 1]));
        asm("fma.rn.f32x2 %0, %1, %2, %3;" : "=l"(P[k])
            : "l"(PB[k]), "l"(f2), "l"(t));
    }
    if (ACC) {
        ull ep = pack2(err, err1);
        asm("fma.rn.f32x2 %0, %1, %2, %3;" : "=l"(acc2)
            : "l"(ep), "l"(ep), "l"(acc2));
    }
}

__global__ void __launch_bounds__(32) fused_kernel(const float* __restrict__ s,
                                                   const float* __restrict__ w_ar,
                                                   const float* __restrict__ w_ma,
                                                   float* __restrict__ out) {
    __shared__ __align__(16) float ss[SS_N];
    __shared__ __align__(16) float xt[TILE_P];
    const int l  = threadIdx.x;
    const int g  = blockIdx.x;
    const int T0 = g * SPAN - WARM;        // global t of tile r=0
    const int sb = T0 - 16;                // ss[i] = s[sb+i]; sb % 16 == 0

    // ---- series segment load ----
    if (g == 0 || g == NWARP - 1) {
        for (int i = l; i < SS_N; i += 32) {
            int p = sb + i;
            p = p < 0 ? 0 : (p > S_LEN ? S_LEN : p);
            ss[i] = s[p];
        }
    } else {
        const float4* src = (const float4*)(s + sb);
        float4* dst = (float4*)ss;
        for (int i = l; i < SS_N / 4; i += 32) dst[i] = src[i];
    }
    __syncwarp();

    // ---- FIR: x[r] = sum_m q[m]*ss[r+m], 18 taps; padded f(r)=r+(r>>6) ----
    {
        float q[18];
        q[0] = w_ar[0];
#pragma unroll
        for (int m = 1; m < 16; ++m) q[m] = w_ar[m] - w_ar[m - 1];
        q[16] = -1.f - w_ar[15];
        q[17] = 1.f;

        for (int e = 0; e < 17; ++e) {
            const int R = 4 * l + 128 * e;         // 4 outputs/lane/pass
            float w[24];
            const float4* sp = (const float4*)(ss + R);
#pragma unroll
            for (int v = 0; v < 6; ++v) {
                float4 t4 = sp[v];
                w[4 * v] = t4.x; w[4 * v + 1] = t4.y;
                w[4 * v + 2] = t4.z; w[4 * v + 3] = t4.w;
            }
            const int fb = R + (R >> 6);           // quad never crosses group
#pragma unroll
            for (int p = 0; p < 4; ++p) {
                float a = 0.f;
#pragma unroll
                for (int m = 0; m < 18; ++m) a = fmaf(q[m], w[p + m], a);
                xt[fb + p] = a;
            }
        }
    }
    __syncwarp();

    // ---- block 0: make tile exact so no guards are needed ----
    if (g == 0) {
        for (int r = l; r < WARM; r += 32)          // t<0: x=0 -> err=0
            xt[r + (r >> 6)] = 0.f;
        if (l <= 16) {
            // t in [0,16]: err_t = y_t (pred suppressed). Feed
            // x~_t = y_t + sum_{j=1..t} c_j*y_{t-j}, c_j = w_ma[16-j],
            // so the unguarded recurrence reproduces err_t = y_t exactly.
            const int t = l;
            float v = ss[t + 113] - ss[t + 112];    // y_t
            for (int j = 1; j <= t; ++j)
                v = fmaf(w_ma[16 - j], ss[t - j + 113] - ss[t - j + 112], v);
            xt[97 + t] = v;                         // f(96+t) = 97+t
        }
    }
    __syncwarp();

    // ---- IIR, packed f32x2, 2 steps/iter ----
    float nc[16];
#pragma unroll
    for (int j = 0; j < 16; ++j) nc[j] = -w_ma[15 - j];
    ull PA[8], PB[8];
#pragma unroll
    for (int k = 0; k < 8; ++k) {
        PA[k] = pack2(nc[2 * k + 1], (2 * k + 2 < 16) ? nc[2 * k + 2] : 0.f);
        PB[k] = pack2(nc[2 * k], nc[2 * k + 1]);
    }
    ull P[9];
#pragma unroll
    for (int k = 0; k < 9; ++k) P[k] = 0ULL;
    ull acc2 = 0ULL;
    const float nc0 = nc[0];

    const int i0 = 65 * l;          // f(64l); groups at +65 each
    const int i1 = i0 + 65;
    const int i2 = i0 + 130;

    // warmup: group0 full (64) + group1 first half (32)
#pragma unroll 8
    for (int ji = 0; ji < 64; ji += 2)
        step2<false>(P, PA, PB, nc0, acc2, xt[i0 + ji], xt[i0 + ji + 1]);
#pragma unroll 8
    for (int ji = 0; ji < 32; ji += 2)
        step2<false>(P, PA, PB, nc0, acc2, xt[i1 + ji], xt[i1 + ji + 1]);
    // main: group1 second half (32) + group2 first half (32)
#pragma unroll 8
    for (int ji = 32; ji < 64; ji += 2)
        step2<true>(P, PA, PB, nc0, acc2, xt[i1 + ji], xt[i1 + ji + 1]);
#pragma unroll 8
    for (int ji = 0; ji < 32; ji += 2)
        step2<true>(P, PA, PB, nc0, acc2, xt[i2 + ji], xt[i2 + ji + 1]);

    float alo, ahi;
    asm("mov.b64 {%0,%1}, %2;" : "=f"(alo), "=f"(ahi) : "l"(acc2));
    float acc = alo + ahi;

#pragma unroll
    for (int off = 16; off; off >>= 1)
        acc += __shfl_down_sync(0xffffffffu, acc, off);

    // ---- last-block-done reduction ----
    unsigned old = 0;
    if (l == 0) {
        g_partial[g] = acc;
        __threadfence();
        old = atomicAdd(&g_cnt, 1u);
    }
    old = __shfl_sync(0xffffffffu, old, 0);
    if (old == NWARP - 1) {
        double v = 0.0;
#pragma unroll
        for (int k = 0; k < NWARP / 32; ++k)
            v += (double)((volatile float*)g_partial)[l + 32 * k];
#pragma unroll
        for (int off = 16; off; off >>= 1)
            v += __shfl_down_sync(0xffffffffu, v, off);
        if (l == 0) {
            out[0] = (float)(v * (1.0 / (double)S_LEN));
            g_cnt = 0;                      // reset for next graph replay
        }
    }
}

extern "C" void kernel_launch(void* const* d_in, const int* in_sizes, int n_in,
                              void* d_out, int out_size) {
    const float* series = (const float*)d_in[0];
    const float* w_ar   = (const float*)d_in[1];
    const float* w_ma   = (const float*)d_in[2];
    float* out = (float*)d_out;
    fused_kernel<<<NWARP, 32>>>(series, w_ar, w_ma, out);
}

// round 6
// speedup vs baseline: 1.3854x; 1.3854x over previous
#include <cuda_runtime.h>

// ARIMA(16,1,16), S = 2^20. One fused kernel, 128 blocks x 128 threads
// (4 warps/block -> all 4 SMSPs used; warp-private smem tiles).
// Per warp: 18-tap FIR (x = y - AR(y) telescoped onto raw series) straight
// from global into smem tile, then order-16 IIR (transposed DF2) with packed
// fma.rn.f32x2, W=64 warmup + L=64 main per lane. Block-0 tile is corrected
// so the unguarded recurrence is exact. Last-block-done reduction in-kernel.

#define S_LEN   1048576
#define WARM    64
#define NWARP   512
#define SPAN    2048                       // main x-values per warp
#define TILE_F  (WARM + SPAN)              // 2112
#define TILE_P  2212                       // covers pass-16 writes f(2175)=2208

typedef unsigned long long ull;

__device__ float    g_partial[NWARP];
__device__ unsigned g_cnt;                 // zero-init; reset by last block

__device__ __forceinline__ ull pack2(float lo, float hi) {
    ull r; asm("mov.b64 %0, {%1,%2};" : "=l"(r) : "f"(lo), "f"(hi)); return r;
}

// 2 IIR steps, state d0..d15 packed into P[0..7], P[8]=(0,0).
// err = x0 + d0; err1 = x1 + d1 + nc0*err;
// d_j' = d_{j+2} + nc_{j+1}*err + nc_j*err1.
template<bool ACC>
__device__ __forceinline__ void step2(ull* P, const ull* PA, const ull* PB,
                                      float nc0, ull& acc2, float x0, float x1) {
    float d0, d1;
    asm("mov.b64 {%0,%1}, %2;" : "=f"(d0), "=f"(d1) : "l"(P[0]));
    float err  = x0 + d0;
    float err1 = fmaf(nc0, err, x1 + d1);
    ull e2 = pack2(err, err);
    ull f2 = pack2(err1, err1);
#pragma unroll
    for (int k = 0; k < 8; ++k) {
        ull t;
        asm("fma.rn.f32x2 %0, %1, %2, %3;" : "=l"(t)
            : "l"(PA[k]), "l"(e2), "l"(P[k + 1]));
        asm("fma.rn.f32x2 %0, %1, %2, %3;" : "=l"(P[k])
            : "l"(PB[k]), "l"(f2), "l"(t));
    }
    if (ACC) {
        ull ep = pack2(err, err1);
        asm("fma.rn.f32x2 %0, %1, %2, %3;" : "=l"(acc2)
            : "l"(ep), "l"(ep), "l"(acc2));
    }
}

__global__ void __launch_bounds__(128) fused_kernel(const float* __restrict__ s,
                                                    const float* __restrict__ w_ar,
                                                    const float* __restrict__ w_ma,
                                                    float* __restrict__ out) {
    __shared__ __align__(16) float xt4[4][TILE_P];
    __shared__ unsigned s_done;
    const int l   = threadIdx.x & 31;
    const int wid = threadIdx.x >> 5;
    const int g   = blockIdx.x * 4 + wid;  // global warp / chunk id
    const int T0  = g * SPAN - WARM;       // global t of tile row 0
    const int sb  = T0 - 16;               // series base; (sb + 4l) 16B-aligned
    float* xt = xt4[wid];

    // ---- FIR: x[r] = sum_{m<18} q[m] * s[sb+r+m]; padded f(r)=r+(r>>6) ----
    {
        float q[18];
        q[0] = w_ar[0];
#pragma unroll
        for (int m = 1; m < 16; ++m) q[m] = w_ar[m] - w_ar[m - 1];
        q[16] = -1.f - w_ar[15];
        q[17] = 1.f;

        const bool edge = (g == 0) | (g == NWARP - 1);
        for (int e = 0; e < 17; ++e) {
            const int R = 4 * l + 128 * e;          // 4 outputs per lane
            float w[24];
            if (edge) {
#pragma unroll
                for (int j = 0; j < 24; ++j) {
                    int p = sb + R + j;
                    p = p < 0 ? 0 : (p > S_LEN ? S_LEN : p);
                    w[j] = s[p];
                }
            } else {
                const float4* sp = (const float4*)(s + sb + R);
#pragma unroll
                for (int v = 0; v < 6; ++v) {
                    float4 t4 = sp[v];
                    w[4 * v] = t4.x; w[4 * v + 1] = t4.y;
                    w[4 * v + 2] = t4.z; w[4 * v + 3] = t4.w;
                }
            }
            const int fb = R + (R >> 6);            // quad never crosses group
#pragma unroll
            for (int p = 0; p < 4; ++p) {
                float a = 0.f;
#pragma unroll
                for (int m = 0; m < 18; ++m) a = fmaf(q[m], w[p + m], a);
                xt[fb + p] = a;
            }
        }
    }
    __syncwarp();

    // ---- block 0: make tile exact (no guards in the recurrence) ----
    if (g == 0) {
        if (l < 32) { xt[l] = 0.f; xt[l + 32] = 0.f; }   // t < 0 -> err = 0
        if (l <= 16) {
            // t in [0,16]: err_t = y_t. Feed x~_t = y_t + sum_{j<=t} c_j*y_{t-j}
            // (c_j = w_ma[16-j]) so the recurrence emits err_t = y_t exactly.
            const int t = l;
            float v = s[t + 1] - s[t];
            for (int j = 1; j <= t; ++j)
                v = fmaf(w_ma[16 - j], s[t - j + 1] - s[t - j], v);
            xt[65 + t];                                  // (no-op read, keep idx clear)
            xt[65 + t] = v;                              // f(64+t) = 65+t
        }
    }
    __syncwarp();

    // ---- IIR, packed f32x2, 2 steps/iter; warm 64 then main 64 ----
    float nc[16];
#pragma unroll
    for (int j = 0; j < 16; ++j) nc[j] = -w_ma[15 - j];
    ull PA[8], PB[8];
#pragma unroll
    for (int k = 0; k < 8; ++k) {
        PA[k] = pack2(nc[2 * k + 1], (2 * k + 2 < 16) ? nc[2 * k + 2] : 0.f);
        PB[k] = pack2(nc[2 * k], nc[2 * k + 1]);
    }
    ull P[9];
#pragma unroll
    for (int k = 0; k < 9; ++k) P[k] = 0ULL;
    ull acc2 = 0ULL;
    const float nc0 = nc[0];

    const int i0 = 65 * l;                  // f(64*l)
    const int i1 = i0 + 65;
#pragma unroll 8
    for (int ji = 0; ji < 64; ji += 2)      // warmup (zero init state)
        step2<false>(P, PA, PB, nc0, acc2, xt[i0 + ji], xt[i0 + ji + 1]);
#pragma unroll 8
    for (int ji = 0; ji < 64; ji += 2)      // main, accumulate err^2
        step2<true>(P, PA, PB, nc0, acc2, xt[i1 + ji], xt[i1 + ji + 1]);

    float alo, ahi;
    asm("mov.b64 {%0,%1}, %2;" : "=f"(alo), "=f"(ahi) : "l"(acc2));
    float acc = alo + ahi;
#pragma unroll
    for (int off = 16; off; off >>= 1)
        acc += __shfl_down_sync(0xffffffffu, acc, off);
    if (l == 0) g_partial[g] = acc;

    // ---- last-block-done final reduction ----
    __threadfence();
    __syncthreads();
    if (threadIdx.x == 0) {
        unsigned old = atomicAdd(&g_cnt, 1u);
        s_done = (old == gridDim.x - 1) ? 1u : 0u;
    }
    __syncthreads();
    if (s_done) {
        double v = 0.0;
#pragma unroll
        for (int k = 0; k < NWARP / 128; ++k)
            v += (double)((volatile float*)g_partial)[threadIdx.x + 128 * k];
#pragma unroll
        for (int off = 16; off; off >>= 1)
            v += __shfl_down_sync(0xffffffffu, v, off);
        __shared__ double sm[4];
        if (l == 0) sm[wid] = v;
        __syncthreads();
        if (threadIdx.x == 0) {
            double w = sm[0] + sm[1] + sm[2] + sm[3];
            out[0] = (float)(w * (1.0 / (double)S_LEN));
            g_cnt = 0;                       // reset for next graph replay
        }
    }
}

extern "C" void kernel_launch(void* const* d_in, const int* in_sizes, int n_in,
                              void* d_out, int out_size) {
    const float* series = (const float*)d_in[0];
    const float* w_ar   = (const float*)d_in[1];
    const float* w_ma   = (const float*)d_in[2];
    float* out = (float*)d_out;
    fused_kernel<<<NWARP / 4, 128>>>(series, w_ar, w_ma, out);
}

// round 7
// speedup vs baseline: 1.4877x; 1.0738x over previous
#include <cuda_runtime.h>

// ARIMA(16,1,16), S = 2^20. One fused kernel, 128 blocks x 256 threads
// (8 warps/block = 2 per SMSP for latency hiding; warp-private smem tiles).
// Per warp: 18-tap FIR (x = y - AR(y) telescoped onto raw series) from global
// into padded smem tile, then order-16 IIR (transposed DF2) with packed
// fma.rn.f32x2, W=64 warmup + L=32 main per lane. Block-0 tile corrected so
// the unguarded recurrence is exact. Last-block-done reduction in-kernel.

#define S_LEN   1048576
#define WARM    64
#define NWARP   1024
#define SPAN    1024                       // main x-values per warp (32 x 32)
#define TILE_F  (WARM + SPAN)              // 1088
#define TILE_P  1188                       // covers f(1151)=1186, pad f(r)=r+(r>>5)
#define WPB     8                          // warps per block

typedef unsigned long long ull;

__device__ float    g_partial[NWARP];
__device__ unsigned g_cnt;                 // zero-init; reset by last block

__device__ __forceinline__ ull pack2(float lo, float hi) {
    ull r; asm("mov.b64 %0, {%1,%2};" : "=l"(r) : "f"(lo), "f"(hi)); return r;
}

// 2 IIR steps, state d0..d15 packed into P[0..7], P[8]=(0,0).
// err = x0 + d0; err1 = x1 + d1 + nc0*err;
// d_j' = d_{j+2} + nc_{j+1}*err + nc_j*err1.
template<bool ACC>
__device__ __forceinline__ void step2(ull* P, const ull* PA, const ull* PB,
                                      float nc0, ull& acc2, float x0, float x1) {
    float d0, d1;
    asm("mov.b64 {%0,%1}, %2;" : "=f"(d0), "=f"(d1) : "l"(P[0]));
    float err  = x0 + d0;
    float err1 = fmaf(nc0, err, x1 + d1);
    ull e2 = pack2(err, err);
    ull f2 = pack2(err1, err1);
#pragma unroll
    for (int k = 0; k < 8; ++k) {
        ull t;
        asm("fma.rn.f32x2 %0, %1, %2, %3;" : "=l"(t)
            : "l"(PA[k]), "l"(e2), "l"(P[k + 1]));
        asm("fma.rn.f32x2 %0, %1, %2, %3;" : "=l"(P[k])
            : "l"(PB[k]), "l"(f2), "l"(t));
    }
    if (ACC) {
        ull ep = pack2(err, err1);
        asm("fma.rn.f32x2 %0, %1, %2, %3;" : "=l"(acc2)
            : "l"(ep), "l"(ep), "l"(acc2));
    }
}

__global__ void __launch_bounds__(256) fused_kernel(const float* __restrict__ s,
                                                    const float* __restrict__ w_ar,
                                                    const float* __restrict__ w_ma,
                                                    float* __restrict__ out) {
    __shared__ __align__(16) float xt4[WPB][TILE_P];
    __shared__ unsigned s_done;
    __shared__ double   sm[WPB];
    const int l   = threadIdx.x & 31;
    const int wid = threadIdx.x >> 5;
    const int g   = blockIdx.x * WPB + wid;   // global warp / chunk-group id
    const int T0  = g * SPAN - WARM;          // global t of tile row 0
    const int sb  = T0 - 16;                  // series base; sb+4l 16B aligned
    float* xt = xt4[wid];

    // ---- FIR: x[r] = sum_{m<18} q[m]*s[sb+r+m]; padded f(r)=r+(r>>5) ----
    {
        float q[18];
        q[0] = w_ar[0];
#pragma unroll
        for (int m = 1; m < 16; ++m) q[m] = w_ar[m] - w_ar[m - 1];
        q[16] = -1.f - w_ar[15];
        q[17] = 1.f;

        const bool edge = (g == 0) | (g == NWARP - 1);
        for (int e = 0; e < 9; ++e) {             // 9*128 = 1152 >= 1088
            const int R = 4 * l + 128 * e;        // 4 outputs per lane
            float w[24];
            if (edge) {
#pragma unroll
                for (int j = 0; j < 24; ++j) {
                    int p = sb + R + j;
                    p = p < 0 ? 0 : (p > S_LEN ? S_LEN : p);
                    w[j] = s[p];
                }
            } else {
                const float4* sp = (const float4*)(s + sb + R);
#pragma unroll
                for (int v = 0; v < 6; ++v) {
                    float4 t4 = sp[v];
                    w[4 * v] = t4.x; w[4 * v + 1] = t4.y;
                    w[4 * v + 2] = t4.z; w[4 * v + 3] = t4.w;
                }
            }
            const int fb = R + (R >> 5);          // quad never crosses group
#pragma unroll
            for (int p = 0; p < 4; ++p) {
                float a = 0.f;
#pragma unroll
                for (int m = 0; m < 18; ++m) a = fmaf(q[m], w[p + m], a);
                xt[fb + p] = a;
            }
        }
    }
    __syncwarp();

    // ---- block-0 warp 0: make tile exact (no guards in recurrence) ----
    if (g == 0) {
        xt[l] = 0.f;                              // r in [0,32): f = r
        xt[33 + l] = 0.f;                         // r in [32,64): f = r+1
        if (l <= 16) {
            // t in [0,16]: err_t = y_t. Feed x~_t = y_t + sum_{j<=t} c_j*y_{t-j}
            // (c_j = w_ma[16-j]) so the recurrence emits err_t = y_t exactly.
            const int t = l;
            float v = s[t + 1] - s[t];
            for (int j = 1; j <= t; ++j)
                v = fmaf(w_ma[16 - j], s[t - j + 1] - s[t - j], v);
            xt[66 + t] = v;                       // f(64+t) = 66+t
        }
    }
    __syncwarp();

    // ---- IIR, packed f32x2, 2 steps/iter; warm 64 then main 32 ----
    float nc[16];
#pragma unroll
    for (int j = 0; j < 16; ++j) nc[j] = -w_ma[15 - j];
    ull PA[8], PB[8];
#pragma unroll
    for (int k = 0; k < 8; ++k) {
        PA[k] = pack2(nc[2 * k + 1], (2 * k + 2 < 16) ? nc[2 * k + 2] : 0.f);
        PB[k] = pack2(nc[2 * k], nc[2 * k + 1]);
    }
    ull P[9];
#pragma unroll
    for (int k = 0; k < 9; ++k) P[k] = 0ULL;
    ull acc2 = 0ULL;
    const float nc0 = nc[0];

    // lane l: warm r in [32l, 64+32l), main r in [64+32l, 96+32l).
    // f-bases per 32-group: b0 = 33l, b1 = b0+33, b2 = b0+66.
    const int b0 = 33 * l;
#pragma unroll
    for (int ji = 0; ji < 32; ji += 2)
        step2<false>(P, PA, PB, nc0, acc2, xt[b0 + ji], xt[b0 + ji + 1]);
#pragma unroll
    for (int ji = 0; ji < 32; ji += 2)
        step2<false>(P, PA, PB, nc0, acc2, xt[b0 + 33 + ji], xt[b0 + 34 + ji]);
#pragma unroll
    for (int ji = 0; ji < 32; ji += 2)
        step2<true>(P, PA, PB, nc0, acc2, xt[b0 + 66 + ji], xt[b0 + 67 + ji]);

    float alo, ahi;
    asm("mov.b64 {%0,%1}, %2;" : "=f"(alo), "=f"(ahi) : "l"(acc2));
    float acc = alo + ahi;
#pragma unroll
    for (int off = 16; off; off >>= 1)
        acc += __shfl_down_sync(0xffffffffu, acc, off);
    if (l == 0) g_partial[g] = acc;

    // ---- last-block-done final reduction ----
    __threadfence();
    __syncthreads();
    if (threadIdx.x == 0) {
        unsigned old = atomicAdd(&g_cnt, 1u);
        s_done = (old == gridDim.x - 1) ? 1u : 0u;
    }
    __syncthreads();
    if (s_done) {
        double v = 0.0;
#pragma unroll
        for (int k = 0; k < NWARP / 256; ++k)
            v += (double)((volatile float*)g_partial)[threadIdx.x + 256 * k];
#pragma unroll
        for (int off = 16; off; off >>= 1)
            v += __shfl_down_sync(0xffffffffu, v, off);
        if (l == 0) sm[wid] = v;
        __syncthreads();
        if (threadIdx.x == 0) {
            double w = 0.0;
#pragma unroll
            for (int k = 0; k < WPB; ++k) w += sm[k];
            out[0] = (float)(w * (1.0 / (double)S_LEN));
            g_cnt = 0;                        // reset for next graph replay
        }
    }
}

extern "C" void kernel_launch(void* const* d_in, const int* in_sizes, int n_in,
                              void* d_out, int out_size) {
    const float* series = (const float*)d_in[0];
    const float* w_ar   = (const float*)d_in[1];
    const float* w_ma   = (const float*)d_in[2];
    float* out = (float*)d_out;
    fused_kernel<<<NWARP / WPB, 256>>>(series, w_ar, w_ma, out);
}

// round 8
// speedup vs baseline: 1.6339x; 1.0983x over previous
#include <cuda_runtime.h>

// ARIMA(16,1,16), S = 2^20. One fused kernel, 256 blocks x 128 threads
// (4 warps/block). Phase 1: block-cooperative batched load of the series
// segment into smem (one high-MLP wait). Phase 2: per-warp 18-tap FIR
// (x = y - AR(y) telescoped onto the raw series) from smem into a padded
// warp-private tile. Phase 3: order-16 IIR (transposed DF2) with packed
// fma.rn.f32x2, W=64 warmup + L=32 main per lane. Block-0 tile corrected so
// the unguarded recurrence is exact. Last-block-done reduction in-kernel.

#define S_LEN   1048576
#define WARM    64
#define NWARP   1024
#define SPAN    1024                       // main x-values per warp (32 x 32)
#define WPB     4                          // warps per block
#define NBLK    (NWARP / WPB)              // 256
#define TILE_F  (WARM + SPAN)              // 1088
#define TILE_P  1188                       // covers f(1151)=1186, f(r)=r+(r>>5)
#define SS_N    4248                       // staged series floats per block

typedef unsigned long long ull;

__device__ float    g_partial[NWARP];
__device__ unsigned g_cnt;                 // zero-init; reset by last block

__device__ __forceinline__ ull pack2(float lo, float hi) {
    ull r; asm("mov.b64 %0, {%1,%2};" : "=l"(r) : "f"(lo), "f"(hi)); return r;
}

// 2 IIR steps, state d0..d15 packed into P[0..7], P[8]=(0,0).
// err = x0 + d0; err1 = x1 + d1 + nc0*err;
// d_j' = d_{j+2} + nc_{j+1}*err + nc_j*err1.
template<bool ACC>
__device__ __forceinline__ void step2(ull* P, const ull* PA, const ull* PB,
                                      float nc0, ull& acc2, float x0, float x1) {
    float d0, d1;
    asm("mov.b64 {%0,%1}, %2;" : "=f"(d0), "=f"(d1) : "l"(P[0]));
    float err  = x0 + d0;
    float err1 = fmaf(nc0, err, x1 + d1);
    ull e2 = pack2(err, err);
    ull f2 = pack2(err1, err1);
#pragma unroll
    for (int k = 0; k < 8; ++k) {
        ull t;
        asm("fma.rn.f32x2 %0, %1, %2, %3;" : "=l"(t)
            : "l"(PA[k]), "l"(e2), "l"(P[k + 1]));
        asm("fma.rn.f32x2 %0, %1, %2, %3;" : "=l"(P[k])
            : "l"(PB[k]), "l"(f2), "l"(t));
    }
    if (ACC) {
        ull ep = pack2(err, err1);
        asm("fma.rn.f32x2 %0, %1, %2, %3;" : "=l"(acc2)
            : "l"(ep), "l"(ep), "l"(acc2));
    }
}

__global__ void __launch_bounds__(128) fused_kernel(const float* __restrict__ s,
                                                    const float* __restrict__ w_ar,
                                                    const float* __restrict__ w_ma,
                                                    float* __restrict__ out) {
    __shared__ __align__(16) float ss[SS_N];
    __shared__ __align__(16) float xt4[WPB][TILE_P];
    __shared__ unsigned s_done;
    __shared__ double   sm[WPB];
    const int l   = threadIdx.x & 31;
    const int wid = threadIdx.x >> 5;
    const int bid = blockIdx.x;
    const int g   = bid * WPB + wid;          // global warp / chunk id
    const int SB  = bid * (WPB * SPAN) - WARM - 16;  // ss[i] = s[SB+i]
    float* xt = xt4[wid];

    // ---- Phase 1: batched cooperative series load (one high-MLP wait) ----
    if (bid == 0 || bid == NBLK - 1) {
        for (int i = threadIdx.x; i < SS_N; i += 128) {
            int p = SB + i;
            p = p < 0 ? 0 : (p > S_LEN ? S_LEN : p);   // s has S_LEN+1 elems
            ss[i] = s[p];
        }
    } else {
        const float4* src = (const float4*)(s + SB);   // SB % 4 == 0
        float4* dst = (float4*)ss;
#pragma unroll
        for (int i = threadIdx.x; i < SS_N / 4; i += 128) dst[i] = src[i];
    }
    __syncthreads();

    // ---- Phase 2: FIR x[r] = sum_{m<18} q[m]*ss[wb+r+m]; f(r)=r+(r>>5) ----
    {
        float q[18];
        q[0] = w_ar[0];
#pragma unroll
        for (int m = 1; m < 16; ++m) q[m] = w_ar[m] - w_ar[m - 1];
        q[16] = -1.f - w_ar[15];
        q[17] = 1.f;

        const int wb = SPAN * wid;                // warp base inside ss
#pragma unroll
        for (int e = 0; e < 9; ++e) {             // 9*128 >= 1088 rows
            const int R = 4 * l + 128 * e;
            float w[24];
            const float4* sp = (const float4*)(ss + wb + R);
#pragma unroll
            for (int v = 0; v < 6; ++v) {
                float4 t4 = sp[v];
                w[4 * v] = t4.x; w[4 * v + 1] = t4.y;
                w[4 * v + 2] = t4.z; w[4 * v + 3] = t4.w;
            }
            const int fb = R + (R >> 5);          // quad never crosses group
#pragma unroll
            for (int p = 0; p < 4; ++p) {
                float a = 0.f;
#pragma unroll
                for (int m = 0; m < 18; ++m) a = fmaf(q[m], w[p + m], a);
                xt[fb + p] = a;
            }
        }
    }
    __syncwarp();

    // ---- block-0 warp-0: make tile exact (no guards in recurrence) ----
    if (g == 0) {
        xt[l] = 0.f;                              // r in [0,32): f = r
        xt[33 + l] = 0.f;                         // r in [32,64): f = r+1
        if (l <= 16) {
            // t in [0,16]: err_t = y_t. Feed x~_t = y_t + sum_{j<=t} c_j*y_{t-j}
            // (c_j = w_ma[16-j]) so the recurrence emits err_t = y_t exactly.
            const int t = l;                      // s[t] = ss[t+80]
            float v = ss[t + 81] - ss[t + 80];
            for (int j = 1; j <= t; ++j)
                v = fmaf(w_ma[16 - j], ss[t - j + 81] - ss[t - j + 80], v);
            xt[66 + t] = v;                       // f(64+t) = 66+t
        }
    }
    __syncwarp();

    // ---- Phase 3: IIR, packed f32x2, 2 steps/iter; warm 64 then main 32 ----
    float nc[16];
#pragma unroll
    for (int j = 0; j < 16; ++j) nc[j] = -w_ma[15 - j];
    ull PA[8], PB[8];
#pragma unroll
    for (int k = 0; k < 8; ++k) {
        PA[k] = pack2(nc[2 * k + 1], (2 * k + 2 < 16) ? nc[2 * k + 2] : 0.f);
        PB[k] = pack2(nc[2 * k], nc[2 * k + 1]);
    }
    ull P[9];
#pragma unroll
    for (int k = 0; k < 9; ++k) P[k] = 0ULL;
    ull acc2 = 0ULL;
    const float nc0 = nc[0];

    const int b0 = 33 * l;                        // f(32*l)
#pragma unroll
    for (int ji = 0; ji < 32; ji += 2)
        step2<false>(P, PA, PB, nc0, acc2, xt[b0 + ji], xt[b0 + ji + 1]);
#pragma unroll
    for (int ji = 0; ji < 32; ji += 2)
        step2<false>(P, PA, PB, nc0, acc2, xt[b0 + 33 + ji], xt[b0 + 34 + ji]);
#pragma unroll
    for (int ji = 0; ji < 32; ji += 2)
        step2<true>(P, PA, PB, nc0, acc2, xt[b0 + 66 + ji], xt[b0 + 67 + ji]);

    float alo, ahi;
    asm("mov.b64 {%0,%1}, %2;" : "=f"(alo), "=f"(ahi) : "l"(acc2));
    float acc = alo + ahi;
#pragma unroll
    for (int off = 16; off; off >>= 1)
        acc += __shfl_down_sync(0xffffffffu, acc, off);
    if (l == 0) g_partial[g] = acc;

    // ---- last-block-done final reduction ----
    __threadfence();
    __syncthreads();
    if (threadIdx.x == 0) {
        unsigned old = atomicAdd(&g_cnt, 1u);
        s_done = (old == gridDim.x - 1) ? 1u : 0u;
    }
    __syncthreads();
    if (s_done) {
        double v = 0.0;
#pragma unroll
        for (int k = 0; k < NWARP / 128; ++k)
            v += (double)((volatile float*)g_partial)[threadIdx.x + 128 * k];
#pragma unroll
        for (int off = 16; off; off >>= 1)
            v += __shfl_down_sync(0xffffffffu, v, off);
        if (l == 0) sm[wid] = v;
        __syncthreads();
        if (threadIdx.x == 0) {
            double w = sm[0] + sm[1] + sm[2] + sm[3];
            out[0] = (float)(w * (1.0 / (double)S_LEN));
            g_cnt = 0;                        // reset for next graph replay
        }
    }
}

extern "C" void kernel_launch(void* const* d_in, const int* in_sizes, int n_in,
                              void* d_out, int out_size) {
    const float* series = (const float*)d_in[0];
    const float* w_ar   = (const float*)d_in[1];
    const float* w_ma   = (const float*)d_in[2];
    float* out = (float*)d_out;
    fused_kernel<<<NBLK, 128>>>(series, w_ar, w_ma, out);
}

// round 10
// speedup vs baseline: 1.6667x; 1.0201x over previous
#include <cuda_runtime.h>

// ARIMA(16,1,16), S = 2^20. One fused kernel, SINGLE WAVE: 128 blocks x 256
// threads (8 warps/block), dynamic smem (block series stage + 8 warp tiles).
// Per warp: packed-f32x2 18-tap FIR (x = y - AR(y) telescoped onto raw
// series) from smem stage into padded warp tile, then order-16 IIR
// (transposed DF2) with packed fma.rn.f32x2, W=48 warmup + L=32 main/lane.
// Block-0 tile corrected so the unguarded recurrence is exact.
// Last-block-done reduction in-kernel.

#define S_LEN   1048576
#define WARM    48
#define NWARP   1024
#define SPAN    1024                       // main x-values per warp (32 x 32)
#define WPB     8
#define NBLK    (NWARP / WPB)              // 128
#define TILE_F  (WARM + SPAN)              // 1072
#define TILE_P  1188                       // covers f(1151)=1186, f(r)=r+(r>>5)
#define SS_N    8340                       // staged series floats (used)
#define SS_F    8352                       // reserved (16B-aligned region)
#define DSMEM_B ((SS_F + WPB * TILE_P) * 4)  // 71424 bytes

typedef unsigned long long ull;

__device__ float    g_partial[NWARP];
__device__ unsigned g_cnt;                 // zero-init; reset by last block

__device__ __forceinline__ ull pack2(float lo, float hi) {
    ull r; asm("mov.b64 %0, {%1,%2};" : "=l"(r) : "f"(lo), "f"(hi)); return r;
}
__device__ __forceinline__ void unpack2(ull v, float& lo, float& hi) {
    asm("mov.b64 {%0,%1}, %2;" : "=f"(lo), "=f"(hi) : "l"(v));
}
__device__ __forceinline__ ull fma2(ull a, ull b, ull c) {
    ull r; asm("fma.rn.f32x2 %0, %1, %2, %3;" : "=l"(r)
               : "l"(a), "l"(b), "l"(c));
    return r;
}

// 2 IIR steps, state d0..d15 packed into P[0..7], P[8]=(0,0).
// err = x0 + d0; err1 = x1 + d1 + nc0*err;
// d_j' = d_{j+2} + nc_{j+1}*err + nc_j*err1.
template<bool ACC>
__device__ __forceinline__ void step2(ull* P, const ull* PA, const ull* PB,
                                      float nc0, ull& acc2, float x0, float x1) {
    float d0, d1;
    unpack2(P[0], d0, d1);
    float err  = x0 + d0;
    float err1 = fmaf(nc0, err, x1 + d1);
    ull e2 = pack2(err, err);
    ull f2 = pack2(err1, err1);
#pragma unroll
    for (int k = 0; k < 8; ++k)
        P[k] = fma2(PB[k], f2, fma2(PA[k], e2, P[k + 1]));
    if (ACC) {
        ull ep = pack2(err, err1);
        acc2 = fma2(ep, ep, acc2);
    }
}

__global__ void __launch_bounds__(256) fused_kernel(const float* __restrict__ s,
                                                    const float* __restrict__ w_ar,
                                                    const float* __restrict__ w_ma,
                                                    float* __restrict__ out) {
    extern __shared__ __align__(16) float dyn[];
    float* ss = dyn;                          // [SS_F]
    __shared__ unsigned s_done;
    __shared__ double   sm[WPB];
    const int l   = threadIdx.x & 31;
    const int wid = threadIdx.x >> 5;
    const int bid = blockIdx.x;
    const int g   = bid * WPB + wid;          // global warp / chunk id
    const int SB  = bid * (WPB * SPAN) - WARM - 16;  // ss[i] = s[SB+i]
    float* xt = dyn + SS_F + wid * TILE_P;

    // ---- Phase 1: batched cooperative series load (one high-MLP wait) ----
    if (bid == 0 || bid == NBLK - 1) {
        for (int i = threadIdx.x; i < SS_N; i += 256) {
            int p = SB + i;
            p = p < 0 ? 0 : (p > S_LEN ? S_LEN : p);   // s has S_LEN+1 elems
            ss[i] = s[p];
        }
    } else {
        const float4* src = (const float4*)(s + SB);   // SB % 4 == 0
        float4* dst = (float4*)ss;
#pragma unroll
        for (int i = threadIdx.x; i < SS_N / 4; i += 256) dst[i] = src[i];
    }
    __syncthreads();

    // ---- Phase 2: packed FIR x[r] = sum_{m<18} q[m]*ss[wb+r+m] ----
    {
        float q[18];
        q[0] = w_ar[0];
#pragma unroll
        for (int m = 1; m < 16; ++m) q[m] = w_ar[m] - w_ar[m - 1];
        q[16] = -1.f - w_ar[15];
        q[17] = 1.f;
        ull q2[18];
#pragma unroll
        for (int m = 0; m < 18; ++m) q2[m] = pack2(q[m], q[m]);

        const int wb = SPAN * wid;                // warp base inside ss
#pragma unroll
        for (int e = 0; e < 9; ++e) {             // 9*128 = 1152 >= 1072 rows
            const int R = 4 * l + 128 * e;
            float w[24];
            const float4* sp = (const float4*)(ss + wb + R);
#pragma unroll
            for (int v = 0; v < 6; ++v) {
                float4 t4 = sp[v];
                w[4 * v] = t4.x; w[4 * v + 1] = t4.y;
                w[4 * v + 2] = t4.z; w[4 * v + 3] = t4.w;
            }
            // A2 = (x[R], x[R+1]), B2 = (x[R+2], x[R+3])
            ull A2 = 0ULL, B2 = 0ULL;
#pragma unroll
            for (int j = 0; j < 20; ++j) {
                ull pj = pack2(w[j], w[j + 1]);
                if (j < 18) A2 = fma2(q2[j], pj, A2);
                if (j >= 2) B2 = fma2(q2[j - 2], pj, B2);
            }
            const int fb = R + (R >> 5);          // quad never crosses group
            float x0, x1, x2, x3;
            unpack2(A2, x0, x1); unpack2(B2, x2, x3);
            xt[fb] = x0; xt[fb + 1] = x1; xt[fb + 2] = x2; xt[fb + 3] = x3;
        }
    }
    __syncwarp();

    // ---- block-0 warp-0: make tile exact (no guards in recurrence) ----
    if (g == 0) {
        xt[l] = 0.f;                              // r in [0,32): f = r
        if (l < 16) xt[33 + l] = 0.f;             // r in [32,48): f = r+1
        if (l <= 16) {
            // t in [0,16]: err_t = y_t. Feed x~_t = y_t + sum_{j<=t} c_j*y_{t-j}
            // (c_j = w_ma[16-j]) so the recurrence emits err_t = y_t exactly.
            const int t = l;                      // s[t] = ss[t+64]
            float v = ss[t + 65] - ss[t + 64];
            for (int j = 1; j <= t; ++j)
                v = fmaf(w_ma[16 - j], ss[t - j + 65] - ss[t - j + 64], v);
            const int r = WARM + t;               // 48+t
            xt[r + (r >> 5)] = v;
        }
    }
    __syncwarp();

    // ---- Phase 3: IIR, packed f32x2; warm 48 steps, main 32 steps ----
    // Lane l: warm rows [32l, 32l+48), main rows [32l+48, 32l+80).
    float nc[16];
#pragma unroll
    for (int j = 0; j < 16; ++j) nc[j] = -w_ma[15 - j];
    ull PA[8], PB[8];
#pragma unroll
    for (int k = 0; k < 8; ++k) {
        PA[k] = pack2(nc[2 * k + 1], (2 * k + 2 < 16) ? nc[2 * k + 2] : 0.f);
        PB[k] = pack2(nc[2 * k], nc[2 * k + 1]);
    }
    ull P[9];
#pragma unroll
    for (int k = 0; k < 9; ++k) P[k] = 0ULL;
    ull acc2 = 0ULL;
    const float nc0 = nc[0];

    const int b0 = 33 * l;                        // f(32*l)
#pragma unroll
    for (int ji = 0; ji < 32; ji += 2)            // warm rows +0..+31
        step2<false>(P, PA, PB, nc0, acc2, xt[b0 + ji], xt[b0 + ji + 1]);
#pragma unroll
    for (int ji = 0; ji < 16; ji += 2)            // warm rows +32..+47
        step2<false>(P, PA, PB, nc0, acc2, xt[b0 + 33 + ji], xt[b0 + 34 + ji]);
#pragma unroll
    for (int ji = 16; ji < 32; ji += 2)           // main rows +48..+63
        step2<true>(P, PA, PB, nc0, acc2, xt[b0 + 33 + ji], xt[b0 + 34 + ji]);
#pragma unroll
    for (int ji = 0; ji < 16; ji += 2)            // main rows +64..+79
        step2<true>(P, PA, PB, nc0, acc2, xt[b0 + 66 + ji], xt[b0 + 67 + ji]);

    float alo, ahi;
    unpack2(acc2, alo, ahi);
    float acc = alo + ahi;
#pragma unroll
    for (int off = 16; off; off >>= 1)
        acc += __shfl_down_sync(0xffffffffu, acc, off);
    if (l == 0) g_partial[g] = acc;

    // ---- last-block-done final reduction ----
    __threadfence();
    __syncthreads();
    if (threadIdx.x == 0) {
        unsigned old = atomicAdd(&g_cnt, 1u);
        s_done = (old == gridDim.x - 1) ? 1u : 0u;
    }
    __syncthreads();
    if (s_done) {
        double v = 0.0;
#pragma unroll
        for (int k = 0; k < NWARP / 256; ++k)
            v += (double)((volatile float*)g_partial)[threadIdx.x + 256 * k];
#pragma unroll
        for (int off = 16; off; off >>= 1)
            v += __shfl_down_sync(0xffffffffu, v, off);
        if (l == 0) sm[wid] = v;
        __syncthreads();
        if (threadIdx.x == 0) {
            double w = 0.0;
#pragma unroll
            for (int k = 0; k < WPB; ++k) w += sm[k];
            out[0] = (float)(w * (1.0 / (double)S_LEN));
            g_cnt = 0;                        // reset for next graph replay
        }
    }
}

extern "C" void kernel_launch(void* const* d_in, const int* in_sizes, int n_in,
                              void* d_out, int out_size) {
    const float* series = (const float*)d_in[0];
    const float* w_ar   = (const float*)d_in[1];
    const float* w_ma   = (const float*)d_in[2];
    float* out = (float*)d_out;
    cudaFuncSetAttribute(fused_kernel,
                         cudaFuncAttributeMaxDynamicSharedMemorySize, DSMEM_B);
    fused_kernel<<<NBLK, 256, DSMEM_B>>>(series, w_ar, w_ma, out);
}